// round 3
// baseline (speedup 1.0000x reference)
#include <cuda_runtime.h>
#include <cuda_bf16.h>
#include <cstdint>

#define NN_NODES 100000
#define EE_EDGES 300000
#define EMB 256
#define NUM_LAYER 5
#define BN_EPS 1e-5f

static inline int cdiv(int a, int b) { return (a + b - 1) / b; }

// ----------------------------------------------------------------------------
// Device scratch (no allocations allowed). NOTE: these symbols are ONLY ever
// referenced from device code — passing them as kernel args from host code
// yields the host shadow address (the round-1 bug).
// ----------------------------------------------------------------------------
__device__ float g_h   [(size_t)NN_NODES * EMB];       // node features (layer input)
__device__ float g_agg [(size_t)NN_NODES * EMB];       // aggregated messages
__device__ float g_hmid[(size_t)NN_NODES * 2 * EMB];   // MLP hidden
__device__ float g_h2  [(size_t)NN_NODES * EMB];       // MLP out (pre-BN)

__device__ int   g_indeg[NN_NODES];
__device__ int   g_off  [NN_NODES];
__device__ int   g_ctr  [NN_NODES];
__device__ int   g_adj  [EE_EDGES];
__device__ int   g_cntb [NN_NODES * 4];   // per-node bond-type counts (bond in 0..3)
__device__ int   g_cntd [NN_NODES * 4];   // per-node dir counts (dir in 0..2)
__device__ float g_stats[2 * EMB];        // [0:256) colsum, [256:512) colsumsq
__device__ float g_scale[EMB];
__device__ float g_shift[EMB];

// ----------------------------------------------------------------------------
// Zero the integer scratch
// ----------------------------------------------------------------------------
__global__ void zero_scratch_kernel() {
    int t = blockIdx.x * blockDim.x + threadIdx.x;
    int stride = gridDim.x * blockDim.x;
    for (int i = t; i < NN_NODES; i += stride) { g_indeg[i] = 0; g_ctr[i] = 0; }
    for (int i = t; i < NN_NODES * 4; i += stride) { g_cntb[i] = 0; g_cntd[i] = 0; }
}

__global__ void zero_stats_kernel() {
    if (threadIdx.x < 2 * EMB) g_stats[threadIdx.x] = 0.0f;
}

// ----------------------------------------------------------------------------
// Edge histogram: in-degree + per-node bond/dir counts
// ----------------------------------------------------------------------------
__global__ void hist_kernel(const int* __restrict__ src, const int* __restrict__ dst,
                            const int* __restrict__ bond, const int* __restrict__ dir) {
    int e = blockIdx.x * blockDim.x + threadIdx.x;
    if (e >= EE_EDGES) return;
    int d = dst[e];
    atomicAdd(&g_indeg[d], 1);
    atomicAdd(&g_cntb[d * 4 + bond[e]], 1);
    atomicAdd(&g_cntd[d * 4 + dir[e]], 1);
}

// ----------------------------------------------------------------------------
// Exclusive scan of indegree -> offsets (single block, carry loop)
// ----------------------------------------------------------------------------
__global__ void scan_kernel() {
    __shared__ int s[1024];
    __shared__ int carry;
    int t = threadIdx.x;
    if (t == 0) carry = 0;
    __syncthreads();
    for (int base = 0; base < NN_NODES; base += 1024) {
        int i = base + t;
        int v = (i < NN_NODES) ? g_indeg[i] : 0;
        s[t] = v;
        __syncthreads();
        #pragma unroll
        for (int off = 1; off < 1024; off <<= 1) {
            int x = (t >= off) ? s[t - off] : 0;
            __syncthreads();
            s[t] += x;
            __syncthreads();
        }
        int incl = s[t];
        int c = carry;
        if (i < NN_NODES) g_off[i] = c + incl - v;
        __syncthreads();
        if (t == 1023) carry = c + s[1023];
        __syncthreads();
    }
}

// ----------------------------------------------------------------------------
// Fill CSR adjacency (src sorted by dst)
// ----------------------------------------------------------------------------
__global__ void fill_kernel(const int* __restrict__ src, const int* __restrict__ dst) {
    int e = blockIdx.x * blockDim.x + threadIdx.x;
    if (e >= EE_EDGES) return;
    int d = dst[e];
    int p = atomicAdd(&g_ctr[d], 1);
    g_adj[g_off[d] + p] = src[e];
}

// ----------------------------------------------------------------------------
// Initial node features: h = atom_emb[x_atom] + chir_emb[x_chir]
// ----------------------------------------------------------------------------
__global__ void init_h_kernel(const int* __restrict__ x_atom, const int* __restrict__ x_chir,
                              const float* __restrict__ atom_emb, const float* __restrict__ chir_emb) {
    int t = blockIdx.x * blockDim.x + threadIdx.x;  // float4 index
    if (t >= NN_NODES * (EMB / 4)) return;
    int row = t >> 6;           // EMB/4 = 64 float4 per row
    int q = t & 63;
    int a = x_atom[row];
    int c = x_chir[row];
    float4 va = reinterpret_cast<const float4*>(atom_emb)[a * 64 + q];
    float4 vc = reinterpret_cast<const float4*>(chir_emb)[c * 64 + q];
    float4 o;
    o.x = va.x + vc.x; o.y = va.y + vc.y; o.z = va.z + vc.z; o.w = va.w + vc.w;
    reinterpret_cast<float4*>(g_h)[t] = o;
}

// ----------------------------------------------------------------------------
// Aggregation: one warp per node.
// agg[i] = h[i] + sum_{j in in(i)} h[j]
//        + BE[4] + sum_b cntb[i][b]*BE[b]           (self loop bond = 4)
//        + (cntd[i][0]+1)*DE[0] + cntd[1]*DE[1] + cntd[2]*DE[2]  (self dir = 0)
// ----------------------------------------------------------------------------
__global__ void agg_kernel(const float* __restrict__ bondE,   // 6x256 (rows 0..4 used)
                           const float* __restrict__ dirE) {  // 3x256
    __shared__ float sBE[5 * EMB];
    __shared__ float sDE[3 * EMB];
    int tid = threadIdx.x;
    for (int i = tid; i < 5 * EMB; i += 256) sBE[i] = bondE[i];
    for (int i = tid; i < 3 * EMB; i += 256) sDE[i] = dirE[i];
    __syncthreads();

    int warp = tid >> 5, lane = tid & 31;
    int node = blockIdx.x * 8 + warp;
    if (node >= NN_NODES) return;
    int c0 = lane * 8;

    const float4* hrow = reinterpret_cast<const float4*>(g_h + (size_t)node * EMB + c0);
    float4 a0 = hrow[0], a1 = hrow[1];
    float acc[8] = {a0.x, a0.y, a0.z, a0.w, a1.x, a1.y, a1.z, a1.w};

    float fb0 = (float)g_cntb[node * 4 + 0];
    float fb1 = (float)g_cntb[node * 4 + 1];
    float fb2 = (float)g_cntb[node * 4 + 2];
    float fb3 = (float)g_cntb[node * 4 + 3];
    float fd0 = (float)g_cntd[node * 4 + 0] + 1.0f;   // + self loop dir 0
    float fd1 = (float)g_cntd[node * 4 + 1];
    float fd2 = (float)g_cntd[node * 4 + 2];

    #pragma unroll
    for (int c = 0; c < 8; c++) {
        int cc = c0 + c;
        float v = sBE[4 * EMB + cc];                  // self loop bond 4
        v += fb0 * sBE[0 * EMB + cc] + fb1 * sBE[1 * EMB + cc]
           + fb2 * sBE[2 * EMB + cc] + fb3 * sBE[3 * EMB + cc];
        v += fd0 * sDE[0 * EMB + cc] + fd1 * sDE[1 * EMB + cc] + fd2 * sDE[2 * EMB + cc];
        acc[c] += v;
    }

    int s = g_off[node];
    int deg = g_indeg[node];
    for (int e = s; e < s + deg; e++) {
        int j = __ldg(&g_adj[e]);
        const float4* hj = reinterpret_cast<const float4*>(g_h + (size_t)j * EMB + c0);
        float4 b0 = hj[0], b1 = hj[1];
        acc[0] += b0.x; acc[1] += b0.y; acc[2] += b0.z; acc[3] += b0.w;
        acc[4] += b1.x; acc[5] += b1.y; acc[6] += b1.z; acc[7] += b1.w;
    }

    float4 o0 = make_float4(acc[0], acc[1], acc[2], acc[3]);
    float4 o1 = make_float4(acc[4], acc[5], acc[6], acc[7]);
    float4* arow = reinterpret_cast<float4*>(g_agg + (size_t)node * EMB + c0);
    arow[0] = o0; arow[1] = o1;
}

// ----------------------------------------------------------------------------
// SGEMM: C[M,NN] = A[M,K] * W^T + bias.  W row-major [NN,K].
// BM=128, BN=64, BK=16, 256 threads, 8x4 per thread.
// SEL picks A/C from device globals (never pass device globals from host!):
//   SEL=0: A=g_agg  [K=256],  C=g_hmid [NCOLS=512]
//   SEL=1: A=g_hmid [K=512],  C=g_h2   [NCOLS=256]
// STATS: also accumulate per-column sum & sumsq into g_stats.
// ----------------------------------------------------------------------------
template <bool RELU, bool STATS, int SEL>
__global__ void __launch_bounds__(256, 2)
gemm_kernel(const float* __restrict__ W, const float* __restrict__ bias) {
    constexpr int M = NN_NODES;
    constexpr int K = (SEL == 0) ? EMB : 2 * EMB;
    constexpr int NCOLS = (SEL == 0) ? 2 * EMB : EMB;
    const float* __restrict__ A = (SEL == 0) ? g_agg : g_hmid;
    float* __restrict__ C = (SEL == 0) ? g_hmid : g_h2;

    constexpr int BM = 128, BN = 64, BK = 16;
    __shared__ float As[BK][BM];
    __shared__ float Bs[BK][BN];
    __shared__ float redS[BN][16];
    __shared__ float redQ[BN][16];

    int tid = threadIdx.x;
    int tx = tid & 15, ty = tid >> 4;
    int rowBase = blockIdx.x * BM;
    int colBase = blockIdx.y * BN;

    float acc[8][4];
    #pragma unroll
    for (int i = 0; i < 8; i++)
        #pragma unroll
        for (int j = 0; j < 4; j++) acc[i][j] = 0.0f;

    for (int k0 = 0; k0 < K; k0 += BK) {
        // load A tile (transposed into As[k][m])
        #pragma unroll
        for (int r = 0; r < 2; r++) {
            int q = tid + 256 * r;          // 0..511 float4 slots
            int row = q >> 2;
            int kq = (q & 3) * 4;
            int grow = rowBase + row;
            float4 v = make_float4(0.f, 0.f, 0.f, 0.f);
            if (grow < M)
                v = *reinterpret_cast<const float4*>(A + (size_t)grow * K + k0 + kq);
            As[kq + 0][row] = v.x; As[kq + 1][row] = v.y;
            As[kq + 2][row] = v.z; As[kq + 3][row] = v.w;
        }
        // load W tile (W is [NCOLS,K] row-major; Bs[k][n] = W[colBase+n][k0+k])
        {
            int n = tid >> 2;
            int kq = (tid & 3) * 4;
            float4 v = *reinterpret_cast<const float4*>(W + (size_t)(colBase + n) * K + k0 + kq);
            Bs[kq + 0][n] = v.x; Bs[kq + 1][n] = v.y;
            Bs[kq + 2][n] = v.z; Bs[kq + 3][n] = v.w;
        }
        __syncthreads();
        #pragma unroll
        for (int k = 0; k < BK; k++) {
            float ra[8], rb[4];
            #pragma unroll
            for (int i = 0; i < 8; i++) ra[i] = As[k][ty + 16 * i];
            #pragma unroll
            for (int j = 0; j < 4; j++) rb[j] = Bs[k][tx + 16 * j];
            #pragma unroll
            for (int i = 0; i < 8; i++)
                #pragma unroll
                for (int j = 0; j < 4; j++) acc[i][j] += ra[i] * rb[j];
        }
        __syncthreads();
    }

    // epilogue
    #pragma unroll
    for (int j = 0; j < 4; j++) {
        int col = colBase + tx + 16 * j;
        float bj = __ldg(&bias[col]);
        float s = 0.f, q = 0.f;
        #pragma unroll
        for (int i = 0; i < 8; i++) {
            int row = rowBase + ty + 16 * i;
            if (row < M) {
                float v = acc[i][j] + bj;
                if (RELU) v = fmaxf(v, 0.f);
                C[(size_t)row * NCOLS + col] = v;
                if (STATS) { s += v; q += v * v; }
            }
        }
        if (STATS) { redS[tx + 16 * j][ty] = s; redQ[tx + 16 * j][ty] = q; }
    }
    if (STATS) {
        __syncthreads();
        if (tid < BN) {
            float s = 0.f, q = 0.f;
            #pragma unroll
            for (int y = 0; y < 16; y++) { s += redS[tid][y]; q += redQ[tid][y]; }
            atomicAdd(&g_stats[colBase + tid], s);
            atomicAdd(&g_stats[EMB + colBase + tid], q);
        }
    }
}

// ----------------------------------------------------------------------------
// BN finalize: scale/shift per column
// ----------------------------------------------------------------------------
__global__ void bn_finalize_kernel(const float* __restrict__ bn_w, const float* __restrict__ bn_b) {
    int c = threadIdx.x;
    if (c >= EMB) return;
    float invN = 1.0f / (float)NN_NODES;
    float mean = g_stats[c] * invN;
    float var = g_stats[EMB + c] * invN - mean * mean;
    float sc = bn_w[c] * rsqrtf(var + BN_EPS);
    g_scale[c] = sc;
    g_shift[c] = bn_b[c] - mean * sc;
}

// ----------------------------------------------------------------------------
// Apply BN affine (+ optional ReLU): dst = [relu](h2 * scale + shift)
// use_ext=1 -> write to harness output; else write to g_h (next layer input).
// ----------------------------------------------------------------------------
__global__ void bn_apply_kernel(float* __restrict__ out_ext, int relu, int use_ext) {
    int t = blockIdx.x * blockDim.x + threadIdx.x;  // float4 idx
    if (t >= NN_NODES * (EMB / 4)) return;
    int q = t & 63;
    float4 v = reinterpret_cast<const float4*>(g_h2)[t];
    float4 sc = reinterpret_cast<const float4*>(g_scale)[q];
    float4 sh = reinterpret_cast<const float4*>(g_shift)[q];
    v.x = v.x * sc.x + sh.x;
    v.y = v.y * sc.y + sh.y;
    v.z = v.z * sc.z + sh.z;
    v.w = v.w * sc.w + sh.w;
    if (relu) {
        v.x = fmaxf(v.x, 0.f); v.y = fmaxf(v.y, 0.f);
        v.z = fmaxf(v.z, 0.f); v.w = fmaxf(v.w, 0.f);
    }
    float4* dst = use_ext ? reinterpret_cast<float4*>(out_ext)
                          : reinterpret_cast<float4*>(g_h);
    dst[t] = v;
}

// ----------------------------------------------------------------------------
// kernel_launch
// ----------------------------------------------------------------------------
extern "C" void kernel_launch(void* const* d_in, const int* in_sizes, int n_in,
                              void* d_out, int out_size) {
    const int*   x_atom    = (const int*)d_in[0];
    const int*   x_chir    = (const int*)d_in[1];
    const int*   edge_idx  = (const int*)d_in[2];    // [2,E]
    const int*   edge_bond = (const int*)d_in[3];
    const int*   edge_dir  = (const int*)d_in[4];
    const float* atom_emb  = (const float*)d_in[5];  // [120,256]
    const float* chir_emb  = (const float*)d_in[6];  // [3,256]
    const float* bond_embs = (const float*)d_in[7];  // [5,6,256]
    const float* dir_embs  = (const float*)d_in[8];  // [5,3,256]
    const float* W1s       = (const float*)d_in[9];  // [5,512,256]
    const float* b1s       = (const float*)d_in[10]; // [5,512]
    const float* W2s       = (const float*)d_in[11]; // [5,256,512]
    const float* b2s       = (const float*)d_in[12]; // [5,256]
    const float* bn_w      = (const float*)d_in[13]; // [5,256]
    const float* bn_b      = (const float*)d_in[14]; // [5,256]
    float* out = (float*)d_out;

    const int* src = edge_idx;
    const int* dst = edge_idx + EE_EDGES;

    // --- preprocessing ---
    zero_scratch_kernel<<<512, 256>>>();
    hist_kernel<<<cdiv(EE_EDGES, 256), 256>>>(src, dst, edge_bond, edge_dir);
    scan_kernel<<<1, 1024>>>();
    fill_kernel<<<cdiv(EE_EDGES, 256), 256>>>(src, dst);
    init_h_kernel<<<cdiv(NN_NODES * (EMB / 4), 256), 256>>>(x_atom, x_chir, atom_emb, chir_emb);

    dim3 g1(cdiv(NN_NODES, 128), 2 * EMB / 64);  // 782 x 8
    dim3 g2(cdiv(NN_NODES, 128), EMB / 64);      // 782 x 4
    int aggBlocks = cdiv(NN_NODES, 8);
    int applyBlocks = cdiv(NN_NODES * (EMB / 4), 256);

    for (int l = 0; l < NUM_LAYER; l++) {
        const float* BE = bond_embs + (size_t)l * 6 * EMB;
        const float* DE = dir_embs + (size_t)l * 3 * EMB;
        const float* W1 = W1s + (size_t)l * 2 * EMB * EMB;
        const float* B1 = b1s + (size_t)l * 2 * EMB;
        const float* W2 = W2s + (size_t)l * EMB * 2 * EMB;
        const float* B2 = b2s + (size_t)l * EMB;

        agg_kernel<<<aggBlocks, 256>>>(BE, DE);
        // hmid = relu(agg @ W1^T + b1)   [N, 512]
        gemm_kernel<true, false, 0><<<g1, 256>>>(W1, B1);
        zero_stats_kernel<<<1, 512>>>();
        // h2 = hmid @ W2^T + b2          [N, 256] (+ column stats)
        gemm_kernel<false, true, 1><<<g2, 256>>>(W2, B2);
        bn_finalize_kernel<<<1, 256>>>(bn_w + l * EMB, bn_b + l * EMB);

        int last = (l == NUM_LAYER - 1);
        bn_apply_kernel<<<applyBlocks, 256>>>(out, last ? 0 : 1, last ? 1 : 0);
    }
}

// round 5
// speedup vs baseline: 1.5037x; 1.5037x over previous
#include <cuda_runtime.h>
#include <cuda_bf16.h>
#include <cstdint>

#define NN_NODES 100000
#define EE_EDGES 300000
#define EMB 256
#define NUM_LAYER 5
#define BN_EPS 1e-5f

static inline int cdiv(int a, int b) { return (a + b - 1) / b; }

// ----------------------------------------------------------------------------
// Device scratch (no allocations allowed). Symbols only referenced from device
// code (host-side use would take the shadow symbol's address).
// ----------------------------------------------------------------------------
__device__ float g_h   [(size_t)NN_NODES * EMB];       // node features (layer input)
__device__ float g_agg [(size_t)NN_NODES * EMB];       // aggregated messages
__device__ float g_hmid[(size_t)NN_NODES * 2 * EMB];   // MLP hidden
__device__ float g_h2  [(size_t)NN_NODES * EMB];       // MLP out (pre-BN)

__device__ int   g_indeg[NN_NODES];
__device__ int   g_off  [NN_NODES];
__device__ int   g_ctr  [NN_NODES];
__device__ int   g_adj  [EE_EDGES];
__device__ int   g_cntb [NN_NODES * 4];
__device__ int   g_cntd [NN_NODES * 4];
__device__ float g_stats[2 * EMB];
__device__ float g_scale[EMB];
__device__ float g_shift[EMB];

// ----------------------------------------------------------------------------
__global__ void zero_scratch_kernel() {
    int t = blockIdx.x * blockDim.x + threadIdx.x;
    int stride = gridDim.x * blockDim.x;
    for (int i = t; i < NN_NODES; i += stride) { g_indeg[i] = 0; g_ctr[i] = 0; }
    for (int i = t; i < NN_NODES * 4; i += stride) { g_cntb[i] = 0; g_cntd[i] = 0; }
}

__global__ void zero_stats_kernel() {
    if (threadIdx.x < 2 * EMB) g_stats[threadIdx.x] = 0.0f;
}

// ----------------------------------------------------------------------------
__global__ void hist_kernel(const int* __restrict__ src, const int* __restrict__ dst,
                            const int* __restrict__ bond, const int* __restrict__ dir) {
    int e = blockIdx.x * blockDim.x + threadIdx.x;
    if (e >= EE_EDGES) return;
    int d = dst[e];
    atomicAdd(&g_indeg[d], 1);
    atomicAdd(&g_cntb[d * 4 + bond[e]], 1);
    atomicAdd(&g_cntd[d * 4 + dir[e]], 1);
}

// ----------------------------------------------------------------------------
__global__ void scan_kernel() {
    __shared__ int s[1024];
    __shared__ int carry;
    int t = threadIdx.x;
    if (t == 0) carry = 0;
    __syncthreads();
    for (int base = 0; base < NN_NODES; base += 1024) {
        int i = base + t;
        int v = (i < NN_NODES) ? g_indeg[i] : 0;
        s[t] = v;
        __syncthreads();
        #pragma unroll
        for (int off = 1; off < 1024; off <<= 1) {
            int x = (t >= off) ? s[t - off] : 0;
            __syncthreads();
            s[t] += x;
            __syncthreads();
        }
        int incl = s[t];
        int c = carry;
        if (i < NN_NODES) g_off[i] = c + incl - v;
        __syncthreads();
        if (t == 1023) carry = c + s[1023];
        __syncthreads();
    }
}

// ----------------------------------------------------------------------------
__global__ void fill_kernel(const int* __restrict__ src, const int* __restrict__ dst) {
    int e = blockIdx.x * blockDim.x + threadIdx.x;
    if (e >= EE_EDGES) return;
    int d = dst[e];
    int p = atomicAdd(&g_ctr[d], 1);
    g_adj[g_off[d] + p] = src[e];
}

// ----------------------------------------------------------------------------
__global__ void init_h_kernel(const int* __restrict__ x_atom, const int* __restrict__ x_chir,
                              const float* __restrict__ atom_emb, const float* __restrict__ chir_emb) {
    int t = blockIdx.x * blockDim.x + threadIdx.x;
    if (t >= NN_NODES * (EMB / 4)) return;
    int row = t >> 6;
    int q = t & 63;
    int a = x_atom[row];
    int c = x_chir[row];
    float4 va = reinterpret_cast<const float4*>(atom_emb)[a * 64 + q];
    float4 vc = reinterpret_cast<const float4*>(chir_emb)[c * 64 + q];
    float4 o;
    o.x = va.x + vc.x; o.y = va.y + vc.y; o.z = va.z + vc.z; o.w = va.w + vc.w;
    reinterpret_cast<float4*>(g_h)[t] = o;
}

// ----------------------------------------------------------------------------
// Aggregation: one warp per node (CSR gather, edge embeddings via counts).
// ----------------------------------------------------------------------------
__global__ void agg_kernel(const float* __restrict__ bondE,   // 6x256 (rows 0..4 used)
                           const float* __restrict__ dirE) {  // 3x256
    __shared__ float sBE[5 * EMB];
    __shared__ float sDE[3 * EMB];
    int tid = threadIdx.x;
    for (int i = tid; i < 5 * EMB; i += 256) sBE[i] = bondE[i];
    for (int i = tid; i < 3 * EMB; i += 256) sDE[i] = dirE[i];
    __syncthreads();

    int warp = tid >> 5, lane = tid & 31;
    int node = blockIdx.x * 8 + warp;
    if (node >= NN_NODES) return;
    int c0 = lane * 8;

    const float4* hrow = reinterpret_cast<const float4*>(g_h + (size_t)node * EMB + c0);
    float4 a0 = hrow[0], a1 = hrow[1];
    float acc[8] = {a0.x, a0.y, a0.z, a0.w, a1.x, a1.y, a1.z, a1.w};

    float fb0 = (float)g_cntb[node * 4 + 0];
    float fb1 = (float)g_cntb[node * 4 + 1];
    float fb2 = (float)g_cntb[node * 4 + 2];
    float fb3 = (float)g_cntb[node * 4 + 3];
    float fd0 = (float)g_cntd[node * 4 + 0] + 1.0f;   // + self loop dir 0
    float fd1 = (float)g_cntd[node * 4 + 1];
    float fd2 = (float)g_cntd[node * 4 + 2];

    #pragma unroll
    for (int c = 0; c < 8; c++) {
        int cc = c0 + c;
        float v = sBE[4 * EMB + cc];                  // self loop bond 4
        v += fb0 * sBE[0 * EMB + cc] + fb1 * sBE[1 * EMB + cc]
           + fb2 * sBE[2 * EMB + cc] + fb3 * sBE[3 * EMB + cc];
        v += fd0 * sDE[0 * EMB + cc] + fd1 * sDE[1 * EMB + cc] + fd2 * sDE[2 * EMB + cc];
        acc[c] += v;
    }

    int s = g_off[node];
    int deg = g_indeg[node];
    for (int e = s; e < s + deg; e++) {
        int j = __ldg(&g_adj[e]);
        const float4* hj = reinterpret_cast<const float4*>(g_h + (size_t)j * EMB + c0);
        float4 b0 = hj[0], b1 = hj[1];
        acc[0] += b0.x; acc[1] += b0.y; acc[2] += b0.z; acc[3] += b0.w;
        acc[4] += b1.x; acc[5] += b1.y; acc[6] += b1.z; acc[7] += b1.w;
    }

    float4 o0 = make_float4(acc[0], acc[1], acc[2], acc[3]);
    float4 o1 = make_float4(acc[4], acc[5], acc[6], acc[7]);
    float4* arow = reinterpret_cast<float4*>(g_agg + (size_t)node * EMB + c0);
    arow[0] = o0; arow[1] = o1;
}

// ----------------------------------------------------------------------------
// 3xTF32 tensor-core GEMM: C = A @ W^T + bias, fp32-level accuracy.
// Split x = hi + lo (hi = tf32(x), lo = tf32(x - hi)); D += Ahi*Bhi + Ahi*Blo
// + Alo*Bhi (lo*lo dropped, ~2^-18 relative).
// Block tile 128x128, BK=16, 256 threads = 8 warps (2x4, warp tile 64x32).
//   SEL=0: A=g_agg  (K=256), C=g_hmid (NC=512)
//   SEL=1: A=g_hmid (K=512), C=g_h2   (NC=256)
// ----------------------------------------------------------------------------
__device__ __forceinline__ uint32_t f2tf32(float x) {
    uint32_t r;
    asm("cvt.rna.tf32.f32 %0, %1;" : "=r"(r) : "f"(x));
    return r;
}

__device__ __forceinline__ void mma_tf32(float d[4], const uint32_t a[4], const uint32_t b[2]) {
    asm volatile(
        "mma.sync.aligned.m16n8k8.row.col.f32.tf32.tf32.f32 "
        "{%0,%1,%2,%3}, {%4,%5,%6,%7}, {%8,%9}, {%0,%1,%2,%3};"
        : "+f"(d[0]), "+f"(d[1]), "+f"(d[2]), "+f"(d[3])
        : "r"(a[0]), "r"(a[1]), "r"(a[2]), "r"(a[3]), "r"(b[0]), "r"(b[1]));
}

__device__ __forceinline__ void split_tf32(float4 v, uint4& hi, uint4& lo) {
    hi.x = f2tf32(v.x); lo.x = f2tf32(v.x - __uint_as_float(hi.x));
    hi.y = f2tf32(v.y); lo.y = f2tf32(v.y - __uint_as_float(hi.y));
    hi.z = f2tf32(v.z); lo.z = f2tf32(v.z - __uint_as_float(hi.z));
    hi.w = f2tf32(v.w); lo.w = f2tf32(v.w - __uint_as_float(hi.w));
}

template <bool RELU, int SEL>
__global__ void __launch_bounds__(256)
gemm_tc_kernel(const float* __restrict__ W, const float* __restrict__ bias) {
    constexpr int M = NN_NODES;
    constexpr int K = (SEL == 0) ? EMB : 2 * EMB;
    constexpr int NC = (SEL == 0) ? 2 * EMB : EMB;
    const float* __restrict__ A = (SEL == 0) ? g_agg : g_hmid;
    float* __restrict__ C = (SEL == 0) ? g_hmid : g_h2;

    constexpr int BM = 128, BN = 128, BK = 16, LDS = BK + 4;  // stride 20
    __shared__ uint32_t AsH[BM][LDS];
    __shared__ uint32_t AsL[BM][LDS];
    __shared__ uint32_t BsH[BN][LDS];
    __shared__ uint32_t BsL[BN][LDS];

    int tid = threadIdx.x;
    int wid = tid >> 5, lane = tid & 31;
    int wm = wid & 1;        // 0..1 : 64-row slab
    int wn = wid >> 1;       // 0..3 : 32-col slab
    int rowBase = blockIdx.x * BM;
    int colBase = blockIdx.y * BN;

    float d[4][4][4];  // [mf][nf][reg]
    #pragma unroll
    for (int i = 0; i < 4; i++)
        #pragma unroll
        for (int j = 0; j < 4; j++)
            #pragma unroll
            for (int r = 0; r < 4; r++) d[i][j][r] = 0.0f;

    int gid = lane >> 2;   // 0..7
    int tig = lane & 3;    // 0..3

    for (int k0 = 0; k0 < K; k0 += BK) {
        // --- stage tiles: 512 float4 slots per matrix, 2 per thread ---
        #pragma unroll
        for (int r = 0; r < 2; r++) {
            int s = tid + 256 * r;
            int row = s >> 2;            // 0..127
            int kq = (s & 3) * 4;
            // A
            int grow = rowBase + row;
            float4 va = (grow < M)
                ? *reinterpret_cast<const float4*>(A + (size_t)grow * K + k0 + kq)
                : make_float4(0.f, 0.f, 0.f, 0.f);
            uint4 hi, lo;
            split_tf32(va, hi, lo);
            *reinterpret_cast<uint4*>(&AsH[row][kq]) = hi;
            *reinterpret_cast<uint4*>(&AsL[row][kq]) = lo;
            // B (W row = output col; NC divisible by 128 so always valid)
            float4 vb = *reinterpret_cast<const float4*>(W + (size_t)(colBase + row) * K + k0 + kq);
            split_tf32(vb, hi, lo);
            *reinterpret_cast<uint4*>(&BsH[row][kq]) = hi;
            *reinterpret_cast<uint4*>(&BsL[row][kq]) = lo;
        }
        __syncthreads();

        #pragma unroll
        for (int kk = 0; kk < BK; kk += 8) {
            uint32_t bh[4][2], bl[4][2];
            #pragma unroll
            for (int nf = 0; nf < 4; nf++) {
                int n = wn * 32 + nf * 8 + gid;
                bh[nf][0] = BsH[n][kk + tig];
                bh[nf][1] = BsH[n][kk + tig + 4];
                bl[nf][0] = BsL[n][kk + tig];
                bl[nf][1] = BsL[n][kk + tig + 4];
            }
            #pragma unroll
            for (int mf = 0; mf < 4; mf++) {
                int r0 = wm * 64 + mf * 16 + gid;
                uint32_t ah[4], al[4];
                ah[0] = AsH[r0][kk + tig];
                ah[1] = AsH[r0 + 8][kk + tig];
                ah[2] = AsH[r0][kk + tig + 4];
                ah[3] = AsH[r0 + 8][kk + tig + 4];
                al[0] = AsL[r0][kk + tig];
                al[1] = AsL[r0 + 8][kk + tig];
                al[2] = AsL[r0][kk + tig + 4];
                al[3] = AsL[r0 + 8][kk + tig + 4];
                #pragma unroll
                for (int nf = 0; nf < 4; nf++) {
                    mma_tf32(d[mf][nf], ah, bh[nf]);   // hi*hi
                    mma_tf32(d[mf][nf], ah, bl[nf]);   // hi*lo
                    mma_tf32(d[mf][nf], al, bh[nf]);   // lo*hi
                }
            }
        }
        __syncthreads();
    }

    // --- epilogue ---
    #pragma unroll
    for (int nf = 0; nf < 4; nf++) {
        int col = colBase + wn * 32 + nf * 8 + tig * 2;
        float b0 = __ldg(&bias[col]);
        float b1 = __ldg(&bias[col + 1]);
        #pragma unroll
        for (int mf = 0; mf < 4; mf++) {
            int row = rowBase + wm * 64 + mf * 16 + gid;
            if (row < M) {
                float v0 = d[mf][nf][0] + b0;
                float v1 = d[mf][nf][1] + b1;
                if (RELU) { v0 = fmaxf(v0, 0.f); v1 = fmaxf(v1, 0.f); }
                C[(size_t)row * NC + col] = v0;
                C[(size_t)row * NC + col + 1] = v1;
            }
            if (row + 8 < M) {
                float v2 = d[mf][nf][2] + b0;
                float v3 = d[mf][nf][3] + b1;
                if (RELU) { v2 = fmaxf(v2, 0.f); v3 = fmaxf(v3, 0.f); }
                C[(size_t)(row + 8) * NC + col] = v2;
                C[(size_t)(row + 8) * NC + col + 1] = v3;
            }
        }
    }
}

// ----------------------------------------------------------------------------
// BN column stats over g_h2 [N, 256].
// ----------------------------------------------------------------------------
__global__ void bn_stats_kernel() {
    int c = threadIdx.x;           // 0..255
    int r0 = blockIdx.x * 256;
    int r1 = min(r0 + 256, NN_NODES);
    float s = 0.f, q = 0.f;
    for (int r = r0; r < r1; r++) {
        float v = g_h2[(size_t)r * EMB + c];
        s += v; q += v * v;
    }
    atomicAdd(&g_stats[c], s);
    atomicAdd(&g_stats[EMB + c], q);
}

// ----------------------------------------------------------------------------
__global__ void bn_finalize_kernel(const float* __restrict__ bn_w, const float* __restrict__ bn_b) {
    int c = threadIdx.x;
    if (c >= EMB) return;
    float invN = 1.0f / (float)NN_NODES;
    float mean = g_stats[c] * invN;
    float var = g_stats[EMB + c] * invN - mean * mean;
    float sc = bn_w[c] * rsqrtf(var + BN_EPS);
    g_scale[c] = sc;
    g_shift[c] = bn_b[c] - mean * sc;
}

// ----------------------------------------------------------------------------
__global__ void bn_apply_kernel(float* __restrict__ out_ext, int relu, int use_ext) {
    int t = blockIdx.x * blockDim.x + threadIdx.x;
    if (t >= NN_NODES * (EMB / 4)) return;
    int q = t & 63;
    float4 v = reinterpret_cast<const float4*>(g_h2)[t];
    float4 sc = reinterpret_cast<const float4*>(g_scale)[q];
    float4 sh = reinterpret_cast<const float4*>(g_shift)[q];
    v.x = v.x * sc.x + sh.x;
    v.y = v.y * sc.y + sh.y;
    v.z = v.z * sc.z + sh.z;
    v.w = v.w * sc.w + sh.w;
    if (relu) {
        v.x = fmaxf(v.x, 0.f); v.y = fmaxf(v.y, 0.f);
        v.z = fmaxf(v.z, 0.f); v.w = fmaxf(v.w, 0.f);
    }
    float4* dst = use_ext ? reinterpret_cast<float4*>(out_ext)
                          : reinterpret_cast<float4*>(g_h);
    dst[t] = v;
}

// ----------------------------------------------------------------------------
extern "C" void kernel_launch(void* const* d_in, const int* in_sizes, int n_in,
                              void* d_out, int out_size) {
    const int*   x_atom    = (const int*)d_in[0];
    const int*   x_chir    = (const int*)d_in[1];
    const int*   edge_idx  = (const int*)d_in[2];    // [2,E]
    const int*   edge_bond = (const int*)d_in[3];
    const int*   edge_dir  = (const int*)d_in[4];
    const float* atom_emb  = (const float*)d_in[5];  // [120,256]
    const float* chir_emb  = (const float*)d_in[6];  // [3,256]
    const float* bond_embs = (const float*)d_in[7];  // [5,6,256]
    const float* dir_embs  = (const float*)d_in[8];  // [5,3,256]
    const float* W1s       = (const float*)d_in[9];  // [5,512,256]
    const float* b1s       = (const float*)d_in[10]; // [5,512]
    const float* W2s       = (const float*)d_in[11]; // [5,256,512]
    const float* b2s       = (const float*)d_in[12]; // [5,256]
    const float* bn_w      = (const float*)d_in[13]; // [5,256]
    const float* bn_b      = (const float*)d_in[14]; // [5,256]
    float* out = (float*)d_out;

    const int* src = edge_idx;
    const int* dst = edge_idx + EE_EDGES;

    // --- preprocessing ---
    zero_scratch_kernel<<<512, 256>>>();
    hist_kernel<<<cdiv(EE_EDGES, 256), 256>>>(src, dst, edge_bond, edge_dir);
    scan_kernel<<<1, 1024>>>();
    fill_kernel<<<cdiv(EE_EDGES, 256), 256>>>(src, dst);
    init_h_kernel<<<cdiv(NN_NODES * (EMB / 4), 256), 256>>>(x_atom, x_chir, atom_emb, chir_emb);

    dim3 g1(cdiv(NN_NODES, 128), 2 * EMB / 128);  // 782 x 4
    dim3 g2(cdiv(NN_NODES, 128), EMB / 128);      // 782 x 2
    int aggBlocks = cdiv(NN_NODES, 8);
    int applyBlocks = cdiv(NN_NODES * (EMB / 4), 256);
    int statBlocks = cdiv(NN_NODES, 256);

    for (int l = 0; l < NUM_LAYER; l++) {
        const float* BE = bond_embs + (size_t)l * 6 * EMB;
        const float* DE = dir_embs + (size_t)l * 3 * EMB;
        const float* W1 = W1s + (size_t)l * 2 * EMB * EMB;
        const float* B1 = b1s + (size_t)l * 2 * EMB;
        const float* W2 = W2s + (size_t)l * EMB * 2 * EMB;
        const float* B2 = b2s + (size_t)l * EMB;

        agg_kernel<<<aggBlocks, 256>>>(BE, DE);
        gemm_tc_kernel<true, 0><<<g1, 256>>>(W1, B1);   // hmid = relu(agg@W1^T+b1)
        gemm_tc_kernel<false, 1><<<g2, 256>>>(W2, B2);  // h2 = hmid@W2^T+b2
        zero_stats_kernel<<<1, 512>>>();
        bn_stats_kernel<<<statBlocks, 256>>>();
        bn_finalize_kernel<<<1, 256>>>(bn_w + l * EMB, bn_b + l * EMB);

        int last = (l == NUM_LAYER - 1);
        bn_apply_kernel<<<applyBlocks, 256>>>(out, last ? 0 : 1, last ? 1 : 0);
    }
}